// round 2
// baseline (speedup 1.0000x reference)
#include <cuda_runtime.h>
#include <cstdint>

#define N_NODES 50000
#define N_EDGES 600000
#define NFEAT 128
#define NGRAPH 64
#define POOL_ROWS 512
#define BM 64
#define GEMM_SMEM ((16384 + 32768 + 128) * 4)

// ---------------- device scratch (static globals; no allocations) ----------------
__device__ int g_deg[N_NODES];
__device__ int g_off[N_NODES + 1];
__device__ int g_pos[N_NODES];
__device__ int g_src[N_EDGES];
__device__ int g_bsums[64];
__device__ float g_mean[(size_t)N_NODES * NFEAT];
__device__ float g_h1[(size_t)N_NODES * NFEAT];
__device__ float g_h2[(size_t)N_NODES * NFEAT];
__device__ unsigned g_pool[NGRAPH * NFEAT];

// ---------------- helpers ----------------
__device__ __forceinline__ unsigned long long pk(float lo, float hi) {
    unsigned long long r;
    asm("mov.b64 %0, {%1, %2};" : "=l"(r) : "f"(lo), "f"(hi));
    return r;
}
__device__ __forceinline__ void fma2(unsigned long long& d, unsigned long long a,
                                     unsigned long long b) {
    asm("fma.rn.f32x2 %0, %1, %2, %0;" : "+l"(d) : "l"(a), "l"(b));
}
__device__ __forceinline__ float2 upk(unsigned long long v) {
    float lo, hi;
    asm("mov.b64 {%0, %1}, %2;" : "=f"(lo), "=f"(hi) : "l"(v));
    return make_float2(lo, hi);
}
__device__ __forceinline__ float lrelu(float v) { return fmaxf(v, 0.01f * v); }

// order-preserving float <-> uint encoding for atomicMax
__device__ __forceinline__ unsigned fenc(float f) {
    unsigned u = __float_as_uint(f);
    return (u & 0x80000000u) ? ~u : (u | 0x80000000u);
}
__device__ __forceinline__ float fdec(unsigned u) {
    return (u & 0x80000000u) ? __uint_as_float(u & 0x7FFFFFFFu) : __uint_as_float(~u);
}

// ---------------- CSR build ----------------
__global__ void k_zero() {
    int i = blockIdx.x * blockDim.x + threadIdx.x;
    if (i < N_NODES) g_deg[i] = 0;
    if (i < NGRAPH * NFEAT) g_pool[i] = 0u;  // 0 < every fenc(real)
}

__global__ void k_hist(const int* __restrict__ ei) {
    int e = blockIdx.x * blockDim.x + threadIdx.x;
    if (e < N_EDGES) {
        int d = ei[N_EDGES + e];
        atomicAdd(&g_deg[d], 1);
    }
}

__global__ void k_scan1() {
    __shared__ int s[1024];
    int t = threadIdx.x;
    int i = blockIdx.x * 1024 + t;
    int v = (i < N_NODES) ? g_deg[i] : 0;
    s[t] = v;
    for (int off = 1; off < 1024; off <<= 1) {
        __syncthreads();
        int tmp = (t >= off) ? s[t - off] : 0;
        __syncthreads();
        s[t] += tmp;
    }
    __syncthreads();
    if (i < N_NODES) g_off[i] = s[t] - v;  // exclusive within chunk
    if (t == 1023) g_bsums[blockIdx.x] = s[1023];
}

__global__ void k_scan2(int nblk) {
    if (threadIdx.x == 0) {
        int run = 0;
        for (int b = 0; b < nblk; b++) {
            int x = g_bsums[b];
            g_bsums[b] = run;
            run += x;
        }
    }
}

__global__ void k_scan3() {
    int i = blockIdx.x * blockDim.x + threadIdx.x;
    if (i < N_NODES) {
        int v = g_off[i] + g_bsums[i >> 10];
        g_off[i] = v;
        g_pos[i] = v;
    }
    if (i == 0) g_off[N_NODES] = N_EDGES;
}

__global__ void k_scatter(const int* __restrict__ ei) {
    int e = blockIdx.x * blockDim.x + threadIdx.x;
    if (e < N_EDGES) {
        int d = ei[N_EDGES + e];
        int s = ei[e];
        int p = atomicAdd(&g_pos[d], 1);
        g_src[p] = s;
    }
}

// ---------------- mean-aggregation: one warp per node, float4 lanes ----------------
__global__ __launch_bounds__(256) void k_agg(const float* __restrict__ in,
                                             float* __restrict__ out) {
    int node = (blockIdx.x * blockDim.x + threadIdx.x) >> 5;
    if (node >= N_NODES) return;
    int lane = threadIdx.x & 31;
    int s0 = g_off[node], s1 = g_off[node + 1];
    float ax = 0.f, ay = 0.f, az = 0.f, aw = 0.f;
    for (int e = s0; e < s1; ++e) {
        int s = g_src[e];
        float4 v = ((const float4*)(in + (size_t)s * NFEAT))[lane];
        ax += v.x; ay += v.y; az += v.z; aw += v.w;
    }
    float inv = 1.0f / (float)max(s1 - s0, 1);
    float4 o = make_float4(ax * inv, ay * inv, az * inv, aw * inv);
    ((float4*)(out + (size_t)node * NFEAT))[lane] = o;
}

// ---------------- fused dual GEMM + bias + leaky_relu ----------------
// out[i][j] = lrelu( sum_k Am[i][k]*Wl[k][j] + sum_k Ax[i][k]*Wr[k][j] + b[j] )
// A tile stored k-major in smem; f32x2 packed FFMA over row pairs.
__global__ __launch_bounds__(256) void k_gemm(const float* __restrict__ Am,
                                              const float* __restrict__ Ax,
                                              const float* __restrict__ Wl,
                                              const float* __restrict__ Wr,
                                              const float* __restrict__ bias,
                                              float* __restrict__ out) {
    extern __shared__ float sm[];
    float* sA = sm;                  // [256 k][64 rows]
    float* sW = sm + 16384;          // [256 k][128 cols]
    float* sB = sm + 16384 + 32768;  // [128]
    int t = threadIdx.x;
    int row0 = blockIdx.x * BM;

    // load combined weights (Wl on top of Wr along k)
    float4* sW4 = (float4*)sW;
    for (int i = t; i < 8192; i += 256) {
        int k = i >> 5, c4 = i & 31;
        const float* src = (k < 128) ? (Wl + k * 128) : (Wr + (k - 128) * 128);
        sW4[i] = ((const float4*)src)[c4];
    }
    if (t < 32) ((float4*)sB)[t] = ((const float4*)bias)[t];

    // load A tile transposed (k-major). row varies fastest -> conflict-free STS.
    for (int i = t; i < 4096; i += 256) {
        int row = i & 63;
        int kq = i >> 6;  // 0..63 float4-quads; first 32 = mean, next 32 = x
        int grow = row0 + row;
        float4 v = make_float4(0.f, 0.f, 0.f, 0.f);
        int kbase;
        if (kq < 32) {
            kbase = kq * 4;
            if (grow < N_NODES) v = ((const float4*)(Am + (size_t)grow * NFEAT))[kq];
        } else {
            kbase = 128 + (kq - 32) * 4;
            if (grow < N_NODES) v = ((const float4*)(Ax + (size_t)grow * NFEAT))[kq - 32];
        }
        sA[(kbase + 0) * 64 + row] = v.x;
        sA[(kbase + 1) * 64 + row] = v.y;
        sA[(kbase + 2) * 64 + row] = v.z;
        sA[(kbase + 3) * 64 + row] = v.w;
    }
    __syncthreads();

    int tx = t & 31;   // col quad: cols tx*4 .. tx*4+3
    int ty = t >> 5;   // row group: rows ty*8 .. ty*8+7
    unsigned long long acc[16];
#pragma unroll
    for (int q = 0; q < 16; q++) acc[q] = 0ull;

    const float4* wp = (const float4*)sW;
#pragma unroll 4
    for (int k = 0; k < 256; ++k) {
        float4 w = wp[k * 32 + tx];
        unsigned long long w0 = pk(w.x, w.x), w1 = pk(w.y, w.y);
        unsigned long long w2 = pk(w.z, w.z), w3 = pk(w.w, w.w);
        const unsigned long long* ap =
            (const unsigned long long*)(sA + k * 64 + ty * 8);
#pragma unroll
        for (int rp = 0; rp < 4; ++rp) {
            unsigned long long a = ap[rp];  // rows (ty*8+2rp, ty*8+2rp+1) packed
            fma2(acc[rp * 4 + 0], a, w0);
            fma2(acc[rp * 4 + 1], a, w1);
            fma2(acc[rp * 4 + 2], a, w2);
            fma2(acc[rp * 4 + 3], a, w3);
        }
    }

    float4 bb = ((float4*)sB)[tx];
#pragma unroll
    for (int rp = 0; rp < 4; ++rp) {
        float2 v0 = upk(acc[rp * 4 + 0]);
        float2 v1 = upk(acc[rp * 4 + 1]);
        float2 v2 = upk(acc[rp * 4 + 2]);
        float2 v3 = upk(acc[rp * 4 + 3]);
        int r0 = row0 + ty * 8 + rp * 2;
        float4 o0 = make_float4(lrelu(v0.x + bb.x), lrelu(v1.x + bb.y),
                                lrelu(v2.x + bb.z), lrelu(v3.x + bb.w));
        float4 o1 = make_float4(lrelu(v0.y + bb.x), lrelu(v1.y + bb.y),
                                lrelu(v2.y + bb.z), lrelu(v3.y + bb.w));
        if (r0 < N_NODES) ((float4*)(out + (size_t)r0 * NFEAT))[tx] = o0;
        if (r0 + 1 < N_NODES) ((float4*)(out + (size_t)(r0 + 1) * NFEAT))[tx] = o1;
    }
}

// ---------------- global max pool (batch sorted -> run-length + atomicMax) ----------
__global__ void k_pool(const float* __restrict__ h, const int* __restrict__ batch) {
    int t = threadIdx.x;  // 0..127 = column
    int r0 = blockIdx.x * POOL_ROWS;
    int r1 = min(r0 + POOL_ROWS, N_NODES);
    if (r0 >= N_NODES) return;
    int curg = batch[r0];
    float m = -3.402823466e38f;
    for (int r = r0; r < r1; ++r) {
        int g = batch[r];
        if (g != curg) {
            atomicMax(&g_pool[curg * NFEAT + t], fenc(m));
            curg = g;
            m = -3.402823466e38f;
        }
        m = fmaxf(m, h[(size_t)r * NFEAT + t]);
    }
    atomicMax(&g_pool[curg * NFEAT + t], fenc(m));
}

// ---------------- final FC: [64,128] @ [128,2] + b ----------------
__global__ void k_fc(const float* __restrict__ Wfc, const float* __restrict__ bfc,
                     float* __restrict__ out) {
    int t = threadIdx.x;  // 0..127
    int g = t >> 1, o = t & 1;
    float s = bfc[o];
#pragma unroll 4
    for (int k = 0; k < 128; k++) s += fdec(g_pool[g * NFEAT + k]) * Wfc[k * 2 + o];
    out[g * 2 + o] = s;
}

// ---------------- launch ----------------
extern "C" void kernel_launch(void* const* d_in, const int* in_sizes, int n_in,
                              void* d_out, int out_size) {
    const float* x = (const float*)d_in[0];
    const int* ei = (const int*)d_in[1];
    const int* batch = (const int*)d_in[2];
    const float* W1l = (const float*)d_in[3];
    const float* b1 = (const float*)d_in[4];
    const float* W1r = (const float*)d_in[5];
    const float* W2l = (const float*)d_in[6];
    const float* b2 = (const float*)d_in[7];
    const float* W2r = (const float*)d_in[8];
    const float* W3l = (const float*)d_in[9];
    const float* b3 = (const float*)d_in[10];
    const float* W3r = (const float*)d_in[11];
    const float* Wfc = (const float*)d_in[12];
    const float* bfc = (const float*)d_in[13];
    float* out = (float*)d_out;

    float *mean, *h1, *h2;
    cudaGetSymbolAddress((void**)&mean, g_mean);
    cudaGetSymbolAddress((void**)&h1, g_h1);
    cudaGetSymbolAddress((void**)&h2, g_h2);

    cudaFuncSetAttribute(k_gemm, cudaFuncAttributeMaxDynamicSharedMemorySize, GEMM_SMEM);

    const int scan_blocks = (N_NODES + 1023) / 1024;  // 49
    const int gemm_blocks = (N_NODES + BM - 1) / BM;  // 782
    const int agg_blocks = (N_NODES * 32 + 255) / 256;

    // CSR build (once; reused by all 3 layers)
    k_zero<<<(N_NODES + 255) / 256, 256>>>();
    k_hist<<<(N_EDGES + 255) / 256, 256>>>(ei);
    k_scan1<<<scan_blocks, 1024>>>();
    k_scan2<<<1, 32>>>(scan_blocks);
    k_scan3<<<(N_NODES + 255) / 256, 256>>>();
    k_scatter<<<(N_EDGES + 255) / 256, 256>>>(ei);

    // layer 1
    k_agg<<<agg_blocks, 256>>>(x, mean);
    k_gemm<<<gemm_blocks, 256, GEMM_SMEM>>>(mean, x, W1l, W1r, b1, h1);
    // layer 2
    k_agg<<<agg_blocks, 256>>>(h1, mean);
    k_gemm<<<gemm_blocks, 256, GEMM_SMEM>>>(mean, h1, W2l, W2r, b2, h2);
    // layer 3
    k_agg<<<agg_blocks, 256>>>(h2, mean);
    k_gemm<<<gemm_blocks, 256, GEMM_SMEM>>>(mean, h2, W3l, W3r, b3, h1);

    // pool + fc
    k_pool<<<(N_NODES + POOL_ROWS - 1) / POOL_ROWS, 128>>>(h1, batch);
    k_fc<<<1, 128>>>(Wfc, bfc, out);
}

// round 4
// speedup vs baseline: 1.1896x; 1.1896x over previous
#include <cuda_runtime.h>
#include <cuda_bf16.h>
#include <cstdint>

#define N_NODES 50000
#define N_EDGES 600000
#define NFEAT 128
#define NGRAPH 64
#define POOL_ROWS 512
#define SCAN_ITEMS 49

// GEMM smem: 4 operand arrays [128 rows][68 u32] (64 kpairs + 4 pad)
#define SM_STRIDE 68
#define SM_ARR (128 * SM_STRIDE)  // 8704 u32
#define GEMM_SMEM (4 * SM_ARR * 4)  // 139264 bytes

// ---------------- device scratch ----------------
__device__ int g_deg[N_NODES];
__device__ int g_off[N_NODES + 1];
__device__ int g_pos[N_NODES];
__device__ int g_src[N_EDGES];
__device__ unsigned g_pool[NGRAPH * NFEAT];
__device__ float g_hf0[(size_t)N_NODES * NFEAT];   // fp32 h ping
__device__ float g_hf1[(size_t)N_NODES * NFEAT];   // fp32 h pong
// bf16 hi/lo operand buffers (uint4-aligned)
__device__ uint4 g_mh4[(size_t)N_NODES * NFEAT / 8];  // mean hi
__device__ uint4 g_ml4[(size_t)N_NODES * NFEAT / 8];  // mean lo
__device__ uint4 g_x0h4[(size_t)N_NODES * NFEAT / 8];
__device__ uint4 g_x0l4[(size_t)N_NODES * NFEAT / 8];
__device__ uint4 g_x1h4[(size_t)N_NODES * NFEAT / 8];
__device__ uint4 g_x1l4[(size_t)N_NODES * NFEAT / 8];
// W split: [3 layers][128 n][256 k] bf16
__device__ uint4 g_Whi4[3 * 128 * 256 / 8];
__device__ uint4 g_Wlo4[3 * 128 * 256 / 8];

// ---------------- helpers ----------------
__device__ __forceinline__ float lrelu(float v) { return fmaxf(v, 0.01f * v); }
__device__ __forceinline__ unsigned fenc(float f) {
    unsigned u = __float_as_uint(f);
    return (u & 0x80000000u) ? ~u : (u | 0x80000000u);
}
__device__ __forceinline__ float fdec(unsigned u) {
    return (u & 0x80000000u) ? __uint_as_float(u & 0x7FFFFFFFu) : __uint_as_float(~u);
}
__device__ __forceinline__ uint32_t pack_hi(float a, float b) {
    __nv_bfloat162 p(__float2bfloat16_rn(a), __float2bfloat16_rn(b));
    return *reinterpret_cast<uint32_t*>(&p);
}
__device__ __forceinline__ uint32_t pack_lo(float a, float b) {
    float ra = a - __bfloat162float(__float2bfloat16_rn(a));
    float rb = b - __bfloat162float(__float2bfloat16_rn(b));
    __nv_bfloat162 p(__float2bfloat16_rn(ra), __float2bfloat16_rn(rb));
    return *reinterpret_cast<uint32_t*>(&p);
}
__device__ __forceinline__ void mma_bf16(float* c, const uint32_t* a, uint32_t b0,
                                         uint32_t b1) {
    asm volatile(
        "mma.sync.aligned.m16n8k16.row.col.f32.bf16.bf16.f32 "
        "{%0,%1,%2,%3}, {%4,%5,%6,%7}, {%8,%9}, {%0,%1,%2,%3};"
        : "+f"(c[0]), "+f"(c[1]), "+f"(c[2]), "+f"(c[3])
        : "r"(a[0]), "r"(a[1]), "r"(a[2]), "r"(a[3]), "r"(b0), "r"(b1));
}

// ---------------- CSR build ----------------
__global__ void k_zero() {
    int i = blockIdx.x * blockDim.x + threadIdx.x;
    if (i < N_NODES) g_deg[i] = 0;
    if (i < NGRAPH * NFEAT) g_pool[i] = 0u;
}

__global__ void k_hist(const int* __restrict__ ei) {
    int e = blockIdx.x * blockDim.x + threadIdx.x;
    if (e < N_EDGES) atomicAdd(&g_deg[ei[N_EDGES + e]], 1);
}

__global__ void k_scan() {
    __shared__ int s[1024];
    int t = threadIdx.x;
    int base = t * SCAN_ITEMS;
    int sum = 0;
    for (int j = 0; j < SCAN_ITEMS; j++) {
        int i = base + j;
        if (i < N_NODES) sum += g_deg[i];
    }
    s[t] = sum;
    for (int off = 1; off < 1024; off <<= 1) {
        __syncthreads();
        int v = (t >= off) ? s[t - off] : 0;
        __syncthreads();
        s[t] += v;
    }
    __syncthreads();
    int run = s[t] - sum;
    for (int j = 0; j < SCAN_ITEMS; j++) {
        int i = base + j;
        if (i < N_NODES) {
            int d = g_deg[i];
            g_off[i] = run;
            g_pos[i] = run;
            run += d;
        }
    }
    if (t == 1023) g_off[N_NODES] = N_EDGES;
}

__global__ void k_scatter(const int* __restrict__ ei) {
    int e = blockIdx.x * blockDim.x + threadIdx.x;
    if (e < N_EDGES) {
        int d = ei[N_EDGES + e];
        int s = ei[e];
        int p = atomicAdd(&g_pos[d], 1);
        g_src[p] = s;
    }
}

// ---------------- W pre-convert: fp32 [k][n] -> bf16 hi/lo [n][256k] ----------------
__global__ void k_wconv(const float* __restrict__ W1l, const float* __restrict__ W1r,
                        const float* __restrict__ W2l, const float* __restrict__ W2r,
                        const float* __restrict__ W3l, const float* __restrict__ W3r) {
    int i = blockIdx.x * blockDim.x + threadIdx.x;
    if (i >= 3 * 128 * 256) return;
    int l = i >> 15;
    int rem = i & 32767;
    int n = rem >> 8;
    int k = rem & 255;
    const float* Wl = (l == 0) ? W1l : (l == 1) ? W2l : W3l;
    const float* Wr = (l == 0) ? W1r : (l == 1) ? W2r : W3r;
    float w = (k < 128) ? Wl[k * 128 + n] : Wr[(k - 128) * 128 + n];
    __nv_bfloat16 h = __float2bfloat16_rn(w);
    ((__nv_bfloat16*)g_Whi4)[i] = h;
    ((__nv_bfloat16*)g_Wlo4)[i] = __float2bfloat16_rn(w - __bfloat162float(h));
}

// ---------------- x -> bf16 hi/lo ----------------
__global__ void k_xconv(const float* __restrict__ x, uint32_t* __restrict__ xh,
                        uint32_t* __restrict__ xl) {
    int i = blockIdx.x * blockDim.x + threadIdx.x;  // per 2 elems
    if (i >= N_NODES * NFEAT / 2) return;
    float2 v = ((const float2*)x)[i];
    xh[i] = pack_hi(v.x, v.y);
    xl[i] = pack_lo(v.x, v.y);
}

// ---------------- mean-aggregation: one warp per node, emits bf16 hi/lo ------------
__global__ __launch_bounds__(256) void k_agg(const float* __restrict__ in,
                                             uint2* __restrict__ oh,
                                             uint2* __restrict__ ol) {
    int node = (blockIdx.x * blockDim.x + threadIdx.x) >> 5;
    if (node >= N_NODES) return;
    int lane = threadIdx.x & 31;
    int s0 = g_off[node], s1 = g_off[node + 1];
    float ax = 0.f, ay = 0.f, az = 0.f, aw = 0.f;
    for (int e = s0; e < s1; ++e) {
        int s = g_src[e];
        float4 v = ((const float4*)(in + (size_t)s * NFEAT))[lane];
        ax += v.x; ay += v.y; az += v.z; aw += v.w;
    }
    float inv = 1.0f / (float)max(s1 - s0, 1);
    ax *= inv; ay *= inv; az *= inv; aw *= inv;
    oh[node * 32 + lane] = make_uint2(pack_hi(ax, ay), pack_hi(az, aw));
    ol[node * 32 + lane] = make_uint2(pack_lo(ax, ay), pack_lo(az, aw));
}

// ---------------- mma.sync dual GEMM (split bf16) + bias + leaky_relu --------------
// out[m][n] = lrelu( sum_{k<128} mean[m][k]*W[n][k] + sum_{k>=128} x[m][k-128]*W[n][k] + b[n] )
__global__ __launch_bounds__(256) void k_gemm(
    const uint4* __restrict__ Amh, const uint4* __restrict__ Aml,
    const uint4* __restrict__ Axh, const uint4* __restrict__ Axl,
    const uint4* __restrict__ Bh, const uint4* __restrict__ Bl,
    const float* __restrict__ bias, float* __restrict__ outf,
    uint32_t* __restrict__ outh, uint32_t* __restrict__ outl) {
    extern __shared__ uint32_t sm[];
    uint32_t* sAh = sm;
    uint32_t* sAl = sm + SM_ARR;
    uint32_t* sBh = sm + 2 * SM_ARR;
    uint32_t* sBl = sm + 3 * SM_ARR;
    int t = threadIdx.x, wid = t >> 5, lane = t & 31;
    int qr = lane >> 2, qc = lane & 3;
    int row0 = blockIdx.x * 128;
    int wrow = (wid & 3) * 32, wcol = (wid >> 2) * 64;

    float acc[2][8][4];
#pragma unroll
    for (int mi = 0; mi < 2; mi++)
#pragma unroll
        for (int ni = 0; ni < 8; ni++)
#pragma unroll
            for (int q = 0; q < 4; q++) acc[mi][ni][q] = 0.f;

    for (int c = 0; c < 2; c++) {
        const uint4* Ah = c ? Axh : Amh;
        const uint4* Al = c ? Axl : Aml;
        // stage A [128 rows][16 uint4] and B chunk
        for (int idx = t; idx < 2048; idx += 256) {
            int r = idx >> 4, c4 = idx & 15;
            int grow = row0 + r;
            uint4 vh = make_uint4(0, 0, 0, 0), vl = vh;
            if (grow < N_NODES) {
                vh = Ah[grow * 16 + c4];
                vl = Al[grow * 16 + c4];
            }
            *(uint4*)(sAh + r * SM_STRIDE + c4 * 4) = vh;
            *(uint4*)(sAl + r * SM_STRIDE + c4 * 4) = vl;
            // B: row n=r, global [n][256k] -> chunk c
            *(uint4*)(sBh + r * SM_STRIDE + c4 * 4) = Bh[r * 32 + c * 16 + c4];
            *(uint4*)(sBl + r * SM_STRIDE + c4 * 4) = Bl[r * 32 + c * 16 + c4];
        }
        __syncthreads();

#pragma unroll
        for (int ks = 0; ks < 8; ks++) {
            int kp = ks * 8 + qc;
            uint32_t ah[2][4], al[2][4];
#pragma unroll
            for (int mi = 0; mi < 2; mi++) {
                int rA = wrow + mi * 16 + qr;
                ah[mi][0] = sAh[rA * SM_STRIDE + kp];
                ah[mi][1] = sAh[(rA + 8) * SM_STRIDE + kp];
                ah[mi][2] = sAh[rA * SM_STRIDE + kp + 4];
                ah[mi][3] = sAh[(rA + 8) * SM_STRIDE + kp + 4];
                al[mi][0] = sAl[rA * SM_STRIDE + kp];
                al[mi][1] = sAl[(rA + 8) * SM_STRIDE + kp];
                al[mi][2] = sAl[rA * SM_STRIDE + kp + 4];
                al[mi][3] = sAl[(rA + 8) * SM_STRIDE + kp + 4];
            }
#pragma unroll
            for (int ni = 0; ni < 8; ni++) {
                int nB = wcol + ni * 8 + qr;
                uint32_t bh0 = sBh[nB * SM_STRIDE + kp];
                uint32_t bh1 = sBh[nB * SM_STRIDE + kp + 4];
                uint32_t bl0 = sBl[nB * SM_STRIDE + kp];
                uint32_t bl1 = sBl[nB * SM_STRIDE + kp + 4];
#pragma unroll
                for (int mi = 0; mi < 2; mi++) {
                    mma_bf16(acc[mi][ni], ah[mi], bh0, bh1);
                    mma_bf16(acc[mi][ni], ah[mi], bl0, bl1);
                    mma_bf16(acc[mi][ni], al[mi], bh0, bh1);
                }
            }
        }
        __syncthreads();
    }

    // epilogue
#pragma unroll
    for (int ni = 0; ni < 8; ni++) {
        int col = wcol + ni * 8 + qc * 2;
        float b0 = __ldg(bias + col), b1 = __ldg(bias + col + 1);
#pragma unroll
        for (int mi = 0; mi < 2; mi++) {
            int r0 = row0 + wrow + mi * 16 + qr;
            float h0 = lrelu(acc[mi][ni][0] + b0);
            float h1 = lrelu(acc[mi][ni][1] + b1);
            float h2 = lrelu(acc[mi][ni][2] + b0);
            float h3 = lrelu(acc[mi][ni][3] + b1);
            if (r0 < N_NODES) {
                *(float2*)(outf + (size_t)r0 * NFEAT + col) = make_float2(h0, h1);
                outh[r0 * 64 + (col >> 1)] = pack_hi(h0, h1);
                outl[r0 * 64 + (col >> 1)] = pack_lo(h0, h1);
            }
            if (r0 + 8 < N_NODES) {
                *(float2*)(outf + (size_t)(r0 + 8) * NFEAT + col) = make_float2(h2, h3);
                outh[(r0 + 8) * 64 + (col >> 1)] = pack_hi(h2, h3);
                outl[(r0 + 8) * 64 + (col >> 1)] = pack_lo(h2, h3);
            }
        }
    }
}

// ---------------- global max pool ----------------
__global__ void k_pool(const float* __restrict__ h, const int* __restrict__ batch) {
    int t = threadIdx.x;
    int r0 = blockIdx.x * POOL_ROWS;
    int r1 = min(r0 + POOL_ROWS, N_NODES);
    if (r0 >= N_NODES) return;
    int curg = batch[r0];
    float m = -3.402823466e38f;
    for (int r = r0; r < r1; ++r) {
        int g = batch[r];
        if (g != curg) {
            atomicMax(&g_pool[curg * NFEAT + t], fenc(m));
            curg = g;
            m = -3.402823466e38f;
        }
        m = fmaxf(m, h[(size_t)r * NFEAT + t]);
    }
    atomicMax(&g_pool[curg * NFEAT + t], fenc(m));
}

// ---------------- final FC ----------------
__global__ void k_fc(const float* __restrict__ Wfc, const float* __restrict__ bfc,
                     float* __restrict__ out) {
    int t = threadIdx.x;
    int g = t >> 1, o = t & 1;
    float s = bfc[o];
#pragma unroll 4
    for (int k = 0; k < 128; k++) s += fdec(g_pool[g * NFEAT + k]) * Wfc[k * 2 + o];
    out[g * 2 + o] = s;
}

// ---------------- launch ----------------
extern "C" void kernel_launch(void* const* d_in, const int* in_sizes, int n_in,
                              void* d_out, int out_size) {
    const float* x = (const float*)d_in[0];
    const int* ei = (const int*)d_in[1];
    const int* batch = (const int*)d_in[2];
    const float* b1 = (const float*)d_in[4];
    const float* b2 = (const float*)d_in[7];
    const float* b3 = (const float*)d_in[10];
    const float* Wfc = (const float*)d_in[12];
    const float* bfc = (const float*)d_in[13];
    float* out = (float*)d_out;

    float *hf0, *hf1;
    uint4 *mh, *ml, *x0h, *x0l, *x1h, *x1l, *whi, *wlo;
    cudaGetSymbolAddress((void**)&hf0, g_hf0);
    cudaGetSymbolAddress((void**)&hf1, g_hf1);
    cudaGetSymbolAddress((void**)&mh, g_mh4);
    cudaGetSymbolAddress((void**)&ml, g_ml4);
    cudaGetSymbolAddress((void**)&x0h, g_x0h4);
    cudaGetSymbolAddress((void**)&x0l, g_x0l4);
    cudaGetSymbolAddress((void**)&x1h, g_x1h4);
    cudaGetSymbolAddress((void**)&x1l, g_x1l4);
    cudaGetSymbolAddress((void**)&whi, g_Whi4);
    cudaGetSymbolAddress((void**)&wlo, g_Wlo4);

    cudaFuncSetAttribute(k_gemm, cudaFuncAttributeMaxDynamicSharedMemorySize, GEMM_SMEM);

    const int gemm_blocks = (N_NODES + 127) / 128;
    const int agg_blocks = (N_NODES * 32 + 255) / 256;
    const int LSTRIDE = 128 * 256 / 8;  // uint4 per layer

    // CSR build (launch order keeps k_agg at index 5 for ncu -s 5)
    k_zero<<<(N_NODES + 255) / 256, 256>>>();
    k_hist<<<(N_EDGES + 255) / 256, 256>>>(ei);
    k_scan<<<1, 1024>>>();
    k_scatter<<<(N_EDGES + 255) / 256, 256>>>(ei);
    k_wconv<<<(3 * 128 * 256 + 255) / 256, 256>>>(
        (const float*)d_in[3], (const float*)d_in[5], (const float*)d_in[6],
        (const float*)d_in[8], (const float*)d_in[9], (const float*)d_in[11]);

    // layer 1
    k_agg<<<agg_blocks, 256>>>(x, (uint2*)mh, (uint2*)ml);
    k_xconv<<<(N_NODES * NFEAT / 2 + 255) / 256, 256>>>(x, (uint32_t*)x0h, (uint32_t*)x0l);
    k_gemm<<<gemm_blocks, 256, GEMM_SMEM>>>(mh, ml, x0h, x0l, whi, wlo, b1, hf1,
                                            (uint32_t*)x1h, (uint32_t*)x1l);
    // layer 2
    k_agg<<<agg_blocks, 256>>>(hf1, (uint2*)mh, (uint2*)ml);
    k_gemm<<<gemm_blocks, 256, GEMM_SMEM>>>(mh, ml, x1h, x1l, whi + LSTRIDE, wlo + LSTRIDE,
                                            b2, hf0, (uint32_t*)x0h, (uint32_t*)x0l);
    // layer 3
    k_agg<<<agg_blocks, 256>>>(hf0, (uint2*)mh, (uint2*)ml);
    k_gemm<<<gemm_blocks, 256, GEMM_SMEM>>>(mh, ml, x0h, x0l, whi + 2 * LSTRIDE,
                                            wlo + 2 * LSTRIDE, b3, hf1, (uint32_t*)x1h,
                                            (uint32_t*)x1l);

    // pool + fc
    k_pool<<<(N_NODES + POOL_ROWS - 1) / POOL_ROWS, 128>>>(hf1, batch);
    k_fc<<<1, 128>>>(Wfc, bfc, out);
}

// round 7
// speedup vs baseline: 1.4739x; 1.2390x over previous
#include <cuda_runtime.h>
#include <cuda_bf16.h>
#include <cstdint>

#define N_NODES 50000
#define N_EDGES 600000
#define NFEAT 128
#define NGRAPH 64
#define POOL_ROWS 256
#define SCAN_ITEMS 49

#define STAGE_BYTES 65536
#define GEMM_SMEM (2 * STAGE_BYTES)

// ---------------- device scratch ----------------
__device__ int g_deg[N_NODES];
__device__ int g_off[N_NODES + 1];
__device__ int g_pos[N_NODES];
__device__ int g_src[N_EDGES];
__device__ unsigned g_pool[NGRAPH * NFEAT];
__device__ float g_hf0[(size_t)N_NODES * NFEAT];
__device__ float g_hf1[(size_t)N_NODES * NFEAT];
// bf16 hi/lo operand buffers: [node][128] bf16 = 256B/row
__device__ uint4 g_mh4[(size_t)N_NODES * NFEAT / 8];
__device__ uint4 g_ml4[(size_t)N_NODES * NFEAT / 8];
__device__ uint4 g_x0h4[(size_t)N_NODES * NFEAT / 8];
__device__ uint4 g_x0l4[(size_t)N_NODES * NFEAT / 8];
__device__ uint4 g_x1h4[(size_t)N_NODES * NFEAT / 8];
__device__ uint4 g_x1l4[(size_t)N_NODES * NFEAT / 8];
// W split: [3 layers][128 n][256 k] bf16 = 512B/row
__device__ uint4 g_Whi4[3 * 128 * 256 / 8];
__device__ uint4 g_Wlo4[3 * 128 * 256 / 8];

// ---------------- helpers ----------------
__device__ __forceinline__ float lrelu(float v) { return fmaxf(v, 0.01f * v); }
__device__ __forceinline__ unsigned fenc(float f) {
    unsigned u = __float_as_uint(f);
    return (u & 0x80000000u) ? ~u : (u | 0x80000000u);
}
__device__ __forceinline__ float fdec(unsigned u) {
    return (u & 0x80000000u) ? __uint_as_float(u & 0x7FFFFFFFu) : __uint_as_float(~u);
}
__device__ __forceinline__ uint32_t pack_hi(float a, float b) {
    __nv_bfloat162 p(__float2bfloat16_rn(a), __float2bfloat16_rn(b));
    return *reinterpret_cast<uint32_t*>(&p);
}
__device__ __forceinline__ uint32_t pack_lo(float a, float b) {
    float ra = a - __bfloat162float(__float2bfloat16_rn(a));
    float rb = b - __bfloat162float(__float2bfloat16_rn(b));
    __nv_bfloat162 p(__float2bfloat16_rn(ra), __float2bfloat16_rn(rb));
    return *reinterpret_cast<uint32_t*>(&p);
}
__device__ __forceinline__ uint32_t smem_u32(const void* p) {
    uint32_t a;
    asm("{ .reg .u64 t; cvta.to.shared.u64 t, %1; cvt.u32.u64 %0, t; }" : "=r"(a) : "l"(p));
    return a;
}
__device__ __forceinline__ void mma_bf16(float* c, const uint32_t* a, uint32_t b0,
                                         uint32_t b1) {
    asm volatile(
        "mma.sync.aligned.m16n8k16.row.col.f32.bf16.bf16.f32 "
        "{%0,%1,%2,%3}, {%4,%5,%6,%7}, {%8,%9}, {%0,%1,%2,%3};"
        : "+f"(c[0]), "+f"(c[1]), "+f"(c[2]), "+f"(c[3])
        : "r"(a[0]), "r"(a[1]), "r"(a[2]), "r"(a[3]), "r"(b0), "r"(b1));
}
__device__ __forceinline__ void ldsm4(uint32_t* r, uint32_t addr) {
    asm volatile("ldmatrix.sync.aligned.m8n8.x4.shared.b16 {%0,%1,%2,%3}, [%4];"
                 : "=r"(r[0]), "=r"(r[1]), "=r"(r[2]), "=r"(r[3]) : "r"(addr));
}
__device__ __forceinline__ void cp16(uint32_t dst, const void* src, int sz) {
    asm volatile("cp.async.ca.shared.global [%0], [%1], 16, %2;"
                 :: "r"(dst), "l"(src), "r"(sz));
}

// ---------------- CSR build ----------------
__global__ void k_hist(const int* __restrict__ ei) {
    int e = blockIdx.x * blockDim.x + threadIdx.x;
    if (e < N_EDGES) atomicAdd(&g_deg[ei[N_EDGES + e]], 1);
}

__global__ void k_scan() {
    __shared__ int s[1024];
    int t = threadIdx.x;
    int base = t * SCAN_ITEMS;
    int sum = 0;
    for (int j = 0; j < SCAN_ITEMS; j++) {
        int i = base + j;
        if (i < N_NODES) sum += g_deg[i];
    }
    s[t] = sum;
    for (int off = 1; off < 1024; off <<= 1) {
        __syncthreads();
        int v = (t >= off) ? s[t - off] : 0;
        __syncthreads();
        s[t] += v;
    }
    __syncthreads();
    int run = s[t] - sum;
    for (int j = 0; j < SCAN_ITEMS; j++) {
        int i = base + j;
        if (i < N_NODES) {
            int d = g_deg[i];
            g_off[i] = run;
            g_pos[i] = run;
            run += d;
        }
    }
    if (t == 1023) g_off[N_NODES] = N_EDGES;
}

__global__ void k_scatter(const int* __restrict__ ei) {
    int e = blockIdx.x * blockDim.x + threadIdx.x;
    if (e < N_EDGES) {
        int d = ei[N_EDGES + e];
        int s = ei[e];
        int p = atomicAdd(&g_pos[d], 1);
        g_src[p] = s;
    }
}

// ---------------- W pre-convert: fp32 [k][n] -> bf16 hi/lo [n][256k] ----------------
__global__ void k_wconv(const float* __restrict__ W1l, const float* __restrict__ W1r,
                        const float* __restrict__ W2l, const float* __restrict__ W2r,
                        const float* __restrict__ W3l, const float* __restrict__ W3r) {
    int i = blockIdx.x * blockDim.x + threadIdx.x;
    if (i >= 3 * 128 * 256) return;
    int l = i >> 15;
    int rem = i & 32767;
    int n = rem >> 8;
    int k = rem & 255;
    const float* Wl = (l == 0) ? W1l : (l == 1) ? W2l : W3l;
    const float* Wr = (l == 0) ? W1r : (l == 1) ? W2r : W3r;
    float w = (k < 128) ? Wl[k * 128 + n] : Wr[(k - 128) * 128 + n];
    __nv_bfloat16 h = __float2bfloat16_rn(w);
    ((__nv_bfloat16*)g_Whi4)[i] = h;
    ((__nv_bfloat16*)g_Wlo4)[i] = __float2bfloat16_rn(w - __bfloat162float(h));
}

// ---------------- mean-aggregation: one warp per node; emits mean hi/lo + self hi/lo
__global__ __launch_bounds__(256) void k_agg(const float* __restrict__ in,
                                             uint2* __restrict__ mh, uint2* __restrict__ ml,
                                             uint2* __restrict__ xh, uint2* __restrict__ xl) {
    int node = (blockIdx.x * blockDim.x + threadIdx.x) >> 5;
    if (node >= N_NODES) return;
    int lane = threadIdx.x & 31;
    // self feature -> x-side bf16 hi/lo
    float4 sv = ((const float4*)(in + (size_t)node * NFEAT))[lane];
    xh[node * 32 + lane] = make_uint2(pack_hi(sv.x, sv.y), pack_hi(sv.z, sv.w));
    xl[node * 32 + lane] = make_uint2(pack_lo(sv.x, sv.y), pack_lo(sv.z, sv.w));
    // neighbor mean
    int s0 = g_off[node], s1 = g_off[node + 1];
    float ax = 0.f, ay = 0.f, az = 0.f, aw = 0.f;
    int e = s0;
    for (; e + 1 < s1; e += 2) {
        int sA = g_src[e], sB = g_src[e + 1];
        float4 v0 = ((const float4*)(in + (size_t)sA * NFEAT))[lane];
        float4 v1 = ((const float4*)(in + (size_t)sB * NFEAT))[lane];
        ax += v0.x + v1.x; ay += v0.y + v1.y; az += v0.z + v1.z; aw += v0.w + v1.w;
    }
    if (e < s1) {
        float4 v = ((const float4*)(in + (size_t)g_src[e] * NFEAT))[lane];
        ax += v.x; ay += v.y; az += v.z; aw += v.w;
    }
    float inv = 1.0f / (float)max(s1 - s0, 1);
    ax *= inv; ay *= inv; az *= inv; aw *= inv;
    mh[node * 32 + lane] = make_uint2(pack_hi(ax, ay), pack_hi(az, aw));
    ml[node * 32 + lane] = make_uint2(pack_lo(ax, ay), pack_lo(az, aw));
}

// ---------------- mma.sync dual GEMM, cp.async double-buffered, ldmatrix ------------
// Tile: 128m x 128n x 256k; 4 k-chunks of 64; 8 warps = 4m x 2n (warp 32m x 64n).
// smem stage (64KB): Ah@0, Al@16K, Bh@32K, Bl@48K; each [128 rows][64 bf16], swizzled.
__global__ __launch_bounds__(256) void k_gemm(
    const uint4* __restrict__ Amh, const uint4* __restrict__ Aml,
    const uint4* __restrict__ Axh, const uint4* __restrict__ Axl,
    const uint4* __restrict__ Bh, const uint4* __restrict__ Bl,
    const float* __restrict__ bias, float* __restrict__ outf) {
    extern __shared__ char smc[];
    uint32_t sb = smem_u32(smc);
    int t = threadIdx.x, lane = t & 31, wid = t >> 5;
    int qr = lane >> 2, qc = lane & 3;
    int row0 = blockIdx.x * 128;
    int wrow = (wid & 3) * 32, wcol = (wid >> 2) * 64;

    float acc[2][4][2][4];
#pragma unroll
    for (int a = 0; a < 2; a++)
#pragma unroll
        for (int b = 0; b < 4; b++)
#pragma unroll
            for (int c = 0; c < 2; c++)
#pragma unroll
                for (int d = 0; d < 4; d++) acc[a][b][c][d] = 0.f;

#define STAGE(CH, BUF)                                                              \
    {                                                                               \
        const int _ch = (CH), _bf = (BUF);                                          \
        const char* abh = (const char*)(_ch < 2 ? Amh : Axh);                       \
        const char* abl = (const char*)(_ch < 2 ? Aml : Axl);                       \
        int kof = (_ch & 1) * 128, bkof = _ch * 128;                                \
        for (int g = t; g < 4096; g += 256) {                                       \
            int arr = g >> 10, idx = g & 1023, row = idx >> 3, c16 = idx & 7;       \
            uint32_t dst = sb + _bf * STAGE_BYTES + arr * 16384 + row * 128 +       \
                           ((c16 ^ (row & 7)) * 16);                                \
            if (arr < 2) {                                                          \
                int grow = row0 + row;                                              \
                const char* src = (arr ? abl : abh) + (size_t)grow * 256 + kof +    \
                                  c16 * 16;                                         \
                cp16(dst, src, grow < N_NODES ? 16 : 0);                            \
            } else {                                                                \
                const char* src = (arr == 2 ? (const char*)Bh : (const char*)Bl) +  \
                                  row * 512 + bkof + c16 * 16;                      \
                cp16(dst, src, 16);                                                 \
            }                                                                       \
        }                                                                           \
        asm volatile("cp.async.commit_group;");                                     \
    }

    STAGE(0, 0);
    for (int ch = 0; ch < 4; ch++) {
        if (ch < 3) {
            STAGE(ch + 1, (ch + 1) & 1);
            asm volatile("cp.async.wait_group 1;");
        } else {
            asm volatile("cp.async.wait_group 0;");
        }
        __syncthreads();
        uint32_t base = sb + (ch & 1) * STAGE_BYTES;
#pragma unroll
        for (int ks = 0; ks < 4; ks++) {
            uint32_t ah[2][4], al[2][4];
#pragma unroll
            for (int mi = 0; mi < 2; mi++) {
                int row = wrow + mi * 16 + (lane & 15);
                int c16 = ks * 2 + (lane >> 4);
                uint32_t ad = base + row * 128 + ((c16 ^ (row & 7)) * 16);
                ldsm4(ah[mi], ad);
                ldsm4(al[mi], ad + 16384);
            }
#pragma unroll
            for (int ni2 = 0; ni2 < 4; ni2++) {
                int row = wcol + ni2 * 16 + (lane & 7) + ((lane >> 4) << 3);
                int c16 = ks * 2 + ((lane >> 3) & 1);
                uint32_t bd = base + 32768 + row * 128 + ((c16 ^ (row & 7)) * 16);
                uint32_t bh[4], bl[4];
                ldsm4(bh, bd);
                ldsm4(bl, bd + 16384);
#pragma unroll
                for (int mi = 0; mi < 2; mi++) {
                    mma_bf16(acc[mi][ni2][0], ah[mi], bh[0], bh[1]);
                    mma_bf16(acc[mi][ni2][0], ah[mi], bl[0], bl[1]);
                    mma_bf16(acc[mi][ni2][0], al[mi], bh[0], bh[1]);
                    mma_bf16(acc[mi][ni2][1], ah[mi], bh[2], bh[3]);
                    mma_bf16(acc[mi][ni2][1], ah[mi], bl[2], bl[3]);
                    mma_bf16(acc[mi][ni2][1], al[mi], bh[2], bh[3]);
                }
            }
        }
        __syncthreads();
    }
#undef STAGE

    // epilogue: bias + leaky_relu, fp32 only
#pragma unroll
    for (int ni2 = 0; ni2 < 4; ni2++)
#pragma unroll
        for (int n8 = 0; n8 < 2; n8++) {
            int col = wcol + ni2 * 16 + n8 * 8 + qc * 2;
            float b0 = __ldg(bias + col), b1 = __ldg(bias + col + 1);
#pragma unroll
            for (int mi = 0; mi < 2; mi++) {
                float* a = acc[mi][ni2][n8];
                int r = row0 + wrow + mi * 16 + qr;
                if (r < N_NODES)
                    *(float2*)(outf + (size_t)r * NFEAT + col) =
                        make_float2(lrelu(a[0] + b0), lrelu(a[1] + b1));
                if (r + 8 < N_NODES)
                    *(float2*)(outf + (size_t)(r + 8) * NFEAT + col) =
                        make_float2(lrelu(a[2] + b0), lrelu(a[3] + b1));
            }
        }
}

// ---------------- global max pool ----------------
__global__ void k_pool(const float* __restrict__ h, const int* __restrict__ batch) {
    int t = threadIdx.x;
    int r0 = blockIdx.x * POOL_ROWS;
    int r1 = min(r0 + POOL_ROWS, N_NODES);
    if (r0 >= N_NODES) return;
    int curg = batch[r0];
    float m = -3.402823466e38f;
    for (int r = r0; r < r1; ++r) {
        int g = batch[r];
        if (g != curg) {
            atomicMax(&g_pool[curg * NFEAT + t], fenc(m));
            curg = g;
            m = -3.402823466e38f;
        }
        m = fmaxf(m, h[(size_t)r * NFEAT + t]);
    }
    atomicMax(&g_pool[curg * NFEAT + t], fenc(m));
}

// ---------------- final FC ----------------
__global__ void k_fc(const float* __restrict__ Wfc, const float* __restrict__ bfc,
                     float* __restrict__ out) {
    int t = threadIdx.x;
    int g = t >> 1, o = t & 1;
    float s = bfc[o];
#pragma unroll 4
    for (int k = 0; k < 128; k++) s += fdec(g_pool[g * NFEAT + k]) * Wfc[k * 2 + o];
    out[g * 2 + o] = s;
}

// ---------------- launch ----------------
extern "C" void kernel_launch(void* const* d_in, const int* in_sizes, int n_in,
                              void* d_out, int out_size) {
    const float* x = (const float*)d_in[0];
    const int* ei = (const int*)d_in[1];
    const int* batch = (const int*)d_in[2];
    const float* b1 = (const float*)d_in[4];
    const float* b2 = (const float*)d_in[7];
    const float* b3 = (const float*)d_in[10];
    const float* Wfc = (const float*)d_in[12];
    const float* bfc = (const float*)d_in[13];
    float* out = (float*)d_out;

    float *hf0, *hf1;
    uint4 *mh, *ml, *x0h, *x0l, *x1h, *x1l, *whi, *wlo;
    int *deg;
    unsigned* pool;
    cudaGetSymbolAddress((void**)&hf0, g_hf0);
    cudaGetSymbolAddress((void**)&hf1, g_hf1);
    cudaGetSymbolAddress((void**)&mh, g_mh4);
    cudaGetSymbolAddress((void**)&ml, g_ml4);
    cudaGetSymbolAddress((void**)&x0h, g_x0h4);
    cudaGetSymbolAddress((void**)&x0l, g_x0l4);
    cudaGetSymbolAddress((void**)&x1h, g_x1h4);
    cudaGetSymbolAddress((void**)&x1l, g_x1l4);
    cudaGetSymbolAddress((void**)&whi, g_Whi4);
    cudaGetSymbolAddress((void**)&wlo, g_Wlo4);
    cudaGetSymbolAddress((void**)&deg, g_deg);
    cudaGetSymbolAddress((void**)&pool, g_pool);

    cudaFuncSetAttribute(k_gemm, cudaFuncAttributeMaxDynamicSharedMemorySize, GEMM_SMEM);

    const int gemm_blocks = (N_NODES + 127) / 128;
    const int agg_blocks = (N_NODES * 32 + 255) / 256;
    const int LSTRIDE = 128 * 256 / 8;  // uint4 per layer

    cudaMemsetAsync(deg, 0, N_NODES * sizeof(int));
    cudaMemsetAsync(pool, 0, NGRAPH * NFEAT * sizeof(unsigned));

    k_wconv<<<(3 * 128 * 256 + 255) / 256, 256>>>(
        (const float*)d_in[3], (const float*)d_in[5], (const float*)d_in[6],
        (const float*)d_in[8], (const float*)d_in[9], (const float*)d_in[11]);
    k_hist<<<(N_EDGES + 255) / 256, 256>>>(ei);
    k_scan<<<1, 1024>>>();
    k_scatter<<<(N_EDGES + 255) / 256, 256>>>(ei);

    // layer 1
    k_agg<<<agg_blocks, 256>>>(x, (uint2*)mh, (uint2*)ml, (uint2*)x0h, (uint2*)x0l);
    k_gemm<<<gemm_blocks, 256, GEMM_SMEM>>>(mh, ml, x0h, x0l, whi, wlo, b1, hf1);
    // layer 2
    k_agg<<<agg_blocks, 256>>>(hf1, (uint2*)mh, (uint2*)ml, (uint2*)x1h, (uint2*)x1l);
    k_gemm<<<gemm_blocks, 256, GEMM_SMEM>>>(mh, ml, x1h, x1l, whi + LSTRIDE,
                                            wlo + LSTRIDE, b2, hf0);
    // layer 3
    k_agg<<<agg_blocks, 256>>>(hf0, (uint2*)mh, (uint2*)ml, (uint2*)x0h, (uint2*)x0l);
    k_gemm<<<gemm_blocks, 256, GEMM_SMEM>>>(mh, ml, x0h, x0l, whi + 2 * LSTRIDE,
                                            wlo + 2 * LSTRIDE, b3, hf1);

    // pool + fc
    k_pool<<<(N_NODES + POOL_ROWS - 1) / POOL_ROWS, 128>>>(hf1, batch);
    k_fc<<<1, 128>>>(Wfc, bfc, out);
}

// round 8
// speedup vs baseline: 1.5424x; 1.0465x over previous
#include <cuda_runtime.h>
#include <cuda_bf16.h>
#include <cstdint>

#define N_NODES 50000
#define N_EDGES 600000
#define NFEAT 128
#define NGRAPH 64
#define POOL_ROWS 256
#define SCAN_ITEMS 49

#define STAGE_BYTES 65536
#define GEMM_SMEM STAGE_BYTES

// ---------------- device scratch ----------------
__device__ int g_deg[N_NODES];
__device__ int g_off[N_NODES + 1];
__device__ int g_pos[N_NODES];
__device__ int g_src[N_EDGES];
__device__ unsigned g_pool[NGRAPH * NFEAT];
__device__ float g_hf0[(size_t)N_NODES * NFEAT];
__device__ float g_hf1[(size_t)N_NODES * NFEAT];
// bf16 hi/lo operand buffers: [node][128] bf16 = 256B/row
__device__ uint4 g_mh4[(size_t)N_NODES * NFEAT / 8];
__device__ uint4 g_ml4[(size_t)N_NODES * NFEAT / 8];
__device__ uint4 g_x0h4[(size_t)N_NODES * NFEAT / 8];
__device__ uint4 g_x0l4[(size_t)N_NODES * NFEAT / 8];
__device__ uint4 g_x1h4[(size_t)N_NODES * NFEAT / 8];
__device__ uint4 g_x1l4[(size_t)N_NODES * NFEAT / 8];
// W split: [3 layers][128 n][256 k] bf16 = 512B/row
__device__ uint4 g_Whi4[3 * 128 * 256 / 8];
__device__ uint4 g_Wlo4[3 * 128 * 256 / 8];

// ---------------- helpers ----------------
__device__ __forceinline__ float lrelu(float v) { return fmaxf(v, 0.01f * v); }
__device__ __forceinline__ unsigned fenc(float f) {
    unsigned u = __float_as_uint(f);
    return (u & 0x80000000u) ? ~u : (u | 0x80000000u);
}
__device__ __forceinline__ float fdec(unsigned u) {
    return (u & 0x80000000u) ? __uint_as_float(u & 0x7FFFFFFFu) : __uint_as_float(~u);
}
__device__ __forceinline__ uint32_t pack_hi(float a, float b) {
    __nv_bfloat162 p(__float2bfloat16_rn(a), __float2bfloat16_rn(b));
    return *reinterpret_cast<uint32_t*>(&p);
}
__device__ __forceinline__ uint32_t pack_lo(float a, float b) {
    float ra = a - __bfloat162float(__float2bfloat16_rn(a));
    float rb = b - __bfloat162float(__float2bfloat16_rn(b));
    __nv_bfloat162 p(__float2bfloat16_rn(ra), __float2bfloat16_rn(rb));
    return *reinterpret_cast<uint32_t*>(&p);
}
__device__ __forceinline__ uint32_t smem_u32(const void* p) {
    uint32_t a;
    asm("{ .reg .u64 t; cvta.to.shared.u64 t, %1; cvt.u32.u64 %0, t; }" : "=r"(a) : "l"(p));
    return a;
}
__device__ __forceinline__ void mma_bf16(float* c, const uint32_t* a, uint32_t b0,
                                         uint32_t b1) {
    asm volatile(
        "mma.sync.aligned.m16n8k16.row.col.f32.bf16.bf16.f32 "
        "{%0,%1,%2,%3}, {%4,%5,%6,%7}, {%8,%9}, {%0,%1,%2,%3};"
        : "+f"(c[0]), "+f"(c[1]), "+f"(c[2]), "+f"(c[3])
        : "r"(a[0]), "r"(a[1]), "r"(a[2]), "r"(a[3]), "r"(b0), "r"(b1));
}
__device__ __forceinline__ void ldsm4(uint32_t* r, uint32_t addr) {
    asm volatile("ldmatrix.sync.aligned.m8n8.x4.shared.b16 {%0,%1,%2,%3}, [%4];"
                 : "=r"(r[0]), "=r"(r[1]), "=r"(r[2]), "=r"(r[3]) : "r"(addr));
}
__device__ __forceinline__ void cp16(uint32_t dst, const void* src, int sz) {
    asm volatile("cp.async.ca.shared.global [%0], [%1], 16, %2;"
                 :: "r"(dst), "l"(src), "r"(sz));
}

// ---------------- W pre-convert + zero deg/pool (fused) ----------------
__global__ void k_wconv(const float* __restrict__ W1l, const float* __restrict__ W1r,
                        const float* __restrict__ W2l, const float* __restrict__ W2r,
                        const float* __restrict__ W3l, const float* __restrict__ W3r) {
    int i = blockIdx.x * blockDim.x + threadIdx.x;
    if (i < N_NODES) g_deg[i] = 0;
    if (i < NGRAPH * NFEAT) g_pool[i] = 0u;
    if (i >= 3 * 128 * 256) return;
    int l = i >> 15;
    int rem = i & 32767;
    int n = rem >> 8;
    int k = rem & 255;
    const float* Wl = (l == 0) ? W1l : (l == 1) ? W2l : W3l;
    const float* Wr = (l == 0) ? W1r : (l == 1) ? W2r : W3r;
    float w = (k < 128) ? Wl[k * 128 + n] : Wr[(k - 128) * 128 + n];
    __nv_bfloat16 h = __float2bfloat16_rn(w);
    ((__nv_bfloat16*)g_Whi4)[i] = h;
    ((__nv_bfloat16*)g_Wlo4)[i] = __float2bfloat16_rn(w - __bfloat162float(h));
}

// ---------------- CSR build (4 edges / thread) ----------------
__global__ void k_hist(const int* __restrict__ ei) {
    int e4 = (blockIdx.x * blockDim.x + threadIdx.x) * 4;
    if (e4 >= N_EDGES) return;
    int4 d = *(const int4*)(ei + N_EDGES + e4);
    atomicAdd(&g_deg[d.x], 1);
    atomicAdd(&g_deg[d.y], 1);
    atomicAdd(&g_deg[d.z], 1);
    atomicAdd(&g_deg[d.w], 1);
}

__global__ void k_scan() {
    __shared__ int s[1024];
    int t = threadIdx.x;
    int base = t * SCAN_ITEMS;
    int sum = 0;
    for (int j = 0; j < SCAN_ITEMS; j++) {
        int i = base + j;
        if (i < N_NODES) sum += g_deg[i];
    }
    s[t] = sum;
    for (int off = 1; off < 1024; off <<= 1) {
        __syncthreads();
        int v = (t >= off) ? s[t - off] : 0;
        __syncthreads();
        s[t] += v;
    }
    __syncthreads();
    int run = s[t] - sum;
    for (int j = 0; j < SCAN_ITEMS; j++) {
        int i = base + j;
        if (i < N_NODES) {
            int d = g_deg[i];
            g_off[i] = run;
            g_pos[i] = run;
            run += d;
        }
    }
    if (t == 1023) g_off[N_NODES] = N_EDGES;
}

__global__ void k_scatter(const int* __restrict__ ei) {
    int e4 = (blockIdx.x * blockDim.x + threadIdx.x) * 4;
    if (e4 >= N_EDGES) return;
    int4 d = *(const int4*)(ei + N_EDGES + e4);
    int4 s = *(const int4*)(ei + e4);
    int p0 = atomicAdd(&g_pos[d.x], 1);
    int p1 = atomicAdd(&g_pos[d.y], 1);
    int p2 = atomicAdd(&g_pos[d.z], 1);
    int p3 = atomicAdd(&g_pos[d.w], 1);
    g_src[p0] = s.x;
    g_src[p1] = s.y;
    g_src[p2] = s.z;
    g_src[p3] = s.w;
}

// ---------------- mean-aggregation: one warp per node; emits mean hi/lo + self hi/lo
__global__ __launch_bounds__(256) void k_agg(const float* __restrict__ in,
                                             uint2* __restrict__ mh, uint2* __restrict__ ml,
                                             uint2* __restrict__ xh, uint2* __restrict__ xl) {
    int node = (blockIdx.x * blockDim.x + threadIdx.x) >> 5;
    if (node >= N_NODES) return;
    int lane = threadIdx.x & 31;
    // self feature -> x-side bf16 hi/lo
    float4 sv = ((const float4*)(in + (size_t)node * NFEAT))[lane];
    xh[node * 32 + lane] = make_uint2(pack_hi(sv.x, sv.y), pack_hi(sv.z, sv.w));
    xl[node * 32 + lane] = make_uint2(pack_lo(sv.x, sv.y), pack_lo(sv.z, sv.w));
    // neighbor mean
    int s0 = g_off[node], s1 = g_off[node + 1];
    float ax = 0.f, ay = 0.f, az = 0.f, aw = 0.f;
    int e = s0;
    for (; e + 1 < s1; e += 2) {
        int sA = g_src[e], sB = g_src[e + 1];
        float4 v0 = ((const float4*)(in + (size_t)sA * NFEAT))[lane];
        float4 v1 = ((const float4*)(in + (size_t)sB * NFEAT))[lane];
        ax += v0.x + v1.x; ay += v0.y + v1.y; az += v0.z + v1.z; aw += v0.w + v1.w;
    }
    if (e < s1) {
        float4 v = ((const float4*)(in + (size_t)g_src[e] * NFEAT))[lane];
        ax += v.x; ay += v.y; az += v.z; aw += v.w;
    }
    float inv = 1.0f / (float)max(s1 - s0, 1);
    ax *= inv; ay *= inv; az *= inv; aw *= inv;
    mh[node * 32 + lane] = make_uint2(pack_hi(ax, ay), pack_hi(az, aw));
    ml[node * 32 + lane] = make_uint2(pack_lo(ax, ay), pack_lo(az, aw));
}

// ---------------- mma.sync dual GEMM, single-stage smem (2 CTA/SM), ldmatrix --------
// Tile: 128m x 128n x 256k; 4 k-chunks of 64; 8 warps = 4m x 2n (warp 32m x 64n).
// smem stage (64KB): Ah@0, Al@16K, Bh@32K, Bl@48K; each [128 rows][64 bf16], swizzled.
__global__ __launch_bounds__(256, 2) void k_gemm(
    const uint4* __restrict__ Amh, const uint4* __restrict__ Aml,
    const uint4* __restrict__ Axh, const uint4* __restrict__ Axl,
    const uint4* __restrict__ Bh, const uint4* __restrict__ Bl,
    const float* __restrict__ bias, float* __restrict__ outf) {
    extern __shared__ char smc[];
    uint32_t sb = smem_u32(smc);
    int t = threadIdx.x, lane = t & 31, wid = t >> 5;
    int qr = lane >> 2, qc = lane & 3;
    int row0 = blockIdx.x * 128;
    int wrow = (wid & 3) * 32, wcol = (wid >> 2) * 64;

    float acc[2][4][2][4];
#pragma unroll
    for (int a = 0; a < 2; a++)
#pragma unroll
        for (int b = 0; b < 4; b++)
#pragma unroll
            for (int c = 0; c < 2; c++)
#pragma unroll
                for (int d = 0; d < 4; d++) acc[a][b][c][d] = 0.f;

#define STAGE(CH)                                                                   \
    {                                                                               \
        const int _ch = (CH);                                                       \
        const char* abh = (const char*)(_ch < 2 ? Amh : Axh);                       \
        const char* abl = (const char*)(_ch < 2 ? Aml : Axl);                       \
        int kof = (_ch & 1) * 128, bkof = _ch * 128;                                \
        for (int g = t; g < 4096; g += 256) {                                       \
            int arr = g >> 10, idx = g & 1023, row = idx >> 3, c16 = idx & 7;       \
            uint32_t dst = sb + arr * 16384 + row * 128 + ((c16 ^ (row & 7)) * 16); \
            if (arr < 2) {                                                          \
                int grow = row0 + row;                                              \
                const char* src = (arr ? abl : abh) + (size_t)grow * 256 + kof +    \
                                  c16 * 16;                                         \
                cp16(dst, src, grow < N_NODES ? 16 : 0);                            \
            } else {                                                                \
                const char* src = (arr == 2 ? (const char*)Bh : (const char*)Bl) +  \
                                  row * 512 + bkof + c16 * 16;                      \
                cp16(dst, src, 16);                                                 \
            }                                                                       \
        }                                                                           \
        asm volatile("cp.async.commit_group;");                                     \
    }

    for (int ch = 0; ch < 4; ch++) {
        STAGE(ch);
        asm volatile("cp.async.wait_group 0;");
        __syncthreads();
        uint32_t base = sb;
#pragma unroll
        for (int ks = 0; ks < 4; ks++) {
            uint32_t ah[2][4], al[2][4];
#pragma unroll
            for (int mi = 0; mi < 2; mi++) {
                int row = wrow + mi * 16 + (lane & 15);
                int c16 = ks * 2 + (lane >> 4);
                uint32_t ad = base + row * 128 + ((c16 ^ (row & 7)) * 16);
                ldsm4(ah[mi], ad);
                ldsm4(al[mi], ad + 16384);
            }
#pragma unroll
            for (int ni2 = 0; ni2 < 4; ni2++) {
                int row = wcol + ni2 * 16 + (lane & 7) + ((lane >> 4) << 3);
                int c16 = ks * 2 + ((lane >> 3) & 1);
                uint32_t bd = base + 32768 + row * 128 + ((c16 ^ (row & 7)) * 16);
                uint32_t bh[4], bl[4];
                ldsm4(bh, bd);
                ldsm4(bl, bd + 16384);
#pragma unroll
                for (int mi = 0; mi < 2; mi++) {
                    mma_bf16(acc[mi][ni2][0], ah[mi], bh[0], bh[1]);
                    mma_bf16(acc[mi][ni2][0], ah[mi], bl[0], bl[1]);
                    mma_bf16(acc[mi][ni2][0], al[mi], bh[0], bh[1]);
                    mma_bf16(acc[mi][ni2][1], ah[mi], bh[2], bh[3]);
                    mma_bf16(acc[mi][ni2][1], ah[mi], bl[2], bl[3]);
                    mma_bf16(acc[mi][ni2][1], al[mi], bh[2], bh[3]);
                }
            }
        }
        __syncthreads();
    }
#undef STAGE

    // epilogue: bias + leaky_relu, fp32 only
#pragma unroll
    for (int ni2 = 0; ni2 < 4; ni2++)
#pragma unroll
        for (int n8 = 0; n8 < 2; n8++) {
            int col = wcol + ni2 * 16 + n8 * 8 + qc * 2;
            float b0 = __ldg(bias + col), b1 = __ldg(bias + col + 1);
#pragma unroll
            for (int mi = 0; mi < 2; mi++) {
                float* a = acc[mi][ni2][n8];
                int r = row0 + wrow + mi * 16 + qr;
                if (r < N_NODES)
                    *(float2*)(outf + (size_t)r * NFEAT + col) =
                        make_float2(lrelu(a[0] + b0), lrelu(a[1] + b1));
                if (r + 8 < N_NODES)
                    *(float2*)(outf + (size_t)(r + 8) * NFEAT + col) =
                        make_float2(lrelu(a[2] + b0), lrelu(a[3] + b1));
            }
        }
}

// ---------------- global max pool ----------------
__global__ void k_pool(const float* __restrict__ h, const int* __restrict__ batch) {
    int t = threadIdx.x;
    int r0 = blockIdx.x * POOL_ROWS;
    int r1 = min(r0 + POOL_ROWS, N_NODES);
    if (r0 >= N_NODES) return;
    int curg = batch[r0];
    float m = -3.402823466e38f;
    for (int r = r0; r < r1; ++r) {
        int g = batch[r];
        if (g != curg) {
            atomicMax(&g_pool[curg * NFEAT + t], fenc(m));
            curg = g;
            m = -3.402823466e38f;
        }
        m = fmaxf(m, h[(size_t)r * NFEAT + t]);
    }
    atomicMax(&g_pool[curg * NFEAT + t], fenc(m));
}

// ---------------- final FC ----------------
__global__ void k_fc(const float* __restrict__ Wfc, const float* __restrict__ bfc,
                     float* __restrict__ out) {
    int t = threadIdx.x;
    int g = t >> 1, o = t & 1;
    float s = bfc[o];
#pragma unroll 4
    for (int k = 0; k < 128; k++) s += fdec(g_pool[g * NFEAT + k]) * Wfc[k * 2 + o];
    out[g * 2 + o] = s;
}

// ---------------- launch ----------------
extern "C" void kernel_launch(void* const* d_in, const int* in_sizes, int n_in,
                              void* d_out, int out_size) {
    const float* x = (const float*)d_in[0];
    const int* ei = (const int*)d_in[1];
    const int* batch = (const int*)d_in[2];
    const float* b1 = (const float*)d_in[4];
    const float* b2 = (const float*)d_in[7];
    const float* b3 = (const float*)d_in[10];
    const float* Wfc = (const float*)d_in[12];
    const float* bfc = (const float*)d_in[13];
    float* out = (float*)d_out;

    float *hf0, *hf1;
    uint4 *mh, *ml, *x0h, *x0l, *x1h, *x1l, *whi, *wlo;
    cudaGetSymbolAddress((void**)&hf0, g_hf0);
    cudaGetSymbolAddress((void**)&hf1, g_hf1);
    cudaGetSymbolAddress((void**)&mh, g_mh4);
    cudaGetSymbolAddress((void**)&ml, g_ml4);
    cudaGetSymbolAddress((void**)&x0h, g_x0h4);
    cudaGetSymbolAddress((void**)&x0l, g_x0l4);
    cudaGetSymbolAddress((void**)&x1h, g_x1h4);
    cudaGetSymbolAddress((void**)&x1l, g_x1l4);
    cudaGetSymbolAddress((void**)&whi, g_Whi4);
    cudaGetSymbolAddress((void**)&wlo, g_Wlo4);

    cudaFuncSetAttribute(k_gemm, cudaFuncAttributeMaxDynamicSharedMemorySize, GEMM_SMEM);

    const int gemm_blocks = (N_NODES + 127) / 128;
    const int agg_blocks = (N_NODES * 32 + 255) / 256;
    const int edge4_blocks = (N_EDGES / 4 + 255) / 256;
    const int LSTRIDE = 128 * 256 / 8;  // uint4 per layer

    // slot 0: wconv (also zeros deg + pool)
    k_wconv<<<(3 * 128 * 256 + 255) / 256, 256>>>(
        (const float*)d_in[3], (const float*)d_in[5], (const float*)d_in[6],
        (const float*)d_in[8], (const float*)d_in[9], (const float*)d_in[11]);
    k_hist<<<edge4_blocks, 256>>>(ei);        // slot 1
    k_scan<<<1, 1024>>>();                    // slot 2
    k_scatter<<<edge4_blocks, 256>>>(ei);     // slot 3

    // layer 1 (agg = slot 4, gemm = slot 5 for ncu)
    k_agg<<<agg_blocks, 256>>>(x, (uint2*)mh, (uint2*)ml, (uint2*)x0h, (uint2*)x0l);
    k_gemm<<<gemm_blocks, 256, GEMM_SMEM>>>(mh, ml, x0h, x0l, whi, wlo, b1, hf1);
    // layer 2
    k_agg<<<agg_blocks, 256>>>(hf1, (uint2*)mh, (uint2*)ml, (uint2*)x1h, (uint2*)x1l);
    k_gemm<<<gemm_blocks, 256, GEMM_SMEM>>>(mh, ml, x1h, x1l, whi + LSTRIDE,
                                            wlo + LSTRIDE, b2, hf0);
    // layer 3
    k_agg<<<agg_blocks, 256>>>(hf0, (uint2*)mh, (uint2*)ml, (uint2*)x0h, (uint2*)x0l);
    k_gemm<<<gemm_blocks, 256, GEMM_SMEM>>>(mh, ml, x0h, x0l, whi + 2 * LSTRIDE,
                                            wlo + 2 * LSTRIDE, b3, hf1);

    // pool + fc
    k_pool<<<(N_NODES + POOL_ROWS - 1) / POOL_ROWS, 128>>>(hf1, batch);
    k_fc<<<1, 128>>>(Wfc, bfc, out);
}